// round 12
// baseline (speedup 1.0000x reference)
#include <cuda_runtime.h>
#include <cuda_fp16.h>
#include <math.h>

#define D         128
#define NCOLS     256
#define MAX_NODES 100000
#define N_CTAS    1563                   // ceil(100000 / 64)
#define SA        136                    // smem A-tile row stride (halves)

typedef unsigned int u32;

// P (layer-1 pre-bias activations, A|B halves; b1 folded into A half), fp16
__device__ __half g_Ph[(size_t)MAX_NODES * NCOLS];
// W1 as paired fp16 B-fragments: ((jp*8 + kb)*32 + lane) -> uint4
__device__ uint4 g_W4[16 * 8 * 32];

// ============================================================================
// helpers
// ============================================================================
__device__ __forceinline__ u32 smem_u32(const void* p) {
    u32 a;
    asm("{ .reg .u64 t; cvta.to.shared.u64 t, %1; cvt.u32.u64 %0, t; }"
        : "=r"(a) : "l"(p));
    return a;
}

__device__ __forceinline__ u32 f2h2(float lo, float hi) {
    u32 r;
    asm("cvt.rn.f16x2.f32 %0, %1, %2;" : "=r"(r) : "f"(hi), "f"(lo));
    return r;
}

#define LDMATRIX_X4(r0, r1, r2, r3, addr)                                   \
    asm volatile("ldmatrix.sync.aligned.m8n8.x4.shared.b16 "                \
                 "{%0, %1, %2, %3}, [%4];"                                  \
                 : "=r"(r0), "=r"(r1), "=r"(r2), "=r"(r3) : "r"(addr))

__device__ __forceinline__ void mma_f16(float* d, const u32* a, u32 b0, u32 b1) {
    asm volatile(
        "mma.sync.aligned.m16n8k16.row.col.f32.f16.f16.f32 "
        "{%0, %1, %2, %3}, {%4, %5, %6, %7}, {%8, %9}, {%0, %1, %2, %3};"
        : "+f"(d[0]), "+f"(d[1]), "+f"(d[2]), "+f"(d[3])
        : "r"(a[0]), "r"(a[1]), "r"(a[2]), "r"(a[3]), "r"(b0), "r"(b1));
}

// ============================================================================
// Kernel 0: W1 -> paired fp16 B-fragments. grid=16 (jp), block=256 (kb,lane).
//   Bmat[n,k] = W1[n,k] (n<128) | W1[n-128, 128+k] (n>=128)
// ============================================================================
__global__ void prep_w_kernel(const float* __restrict__ W1)
{
    const int jp   = blockIdx.x;
    const int kb   = threadIdx.x >> 5;
    const int lane = threadIdx.x & 31;
    const int n0   = jp * 16 + (lane >> 2);
    const int n1   = n0 + 8;
    const int k0   = kb * 16 + (lane & 3) * 2;

    const float* r0 = (n0 < 128) ? (W1 + (size_t)n0 * NCOLS)
                                 : (W1 + (size_t)(n0 - 128) * NCOLS + 128);
    const float* r1 = (n1 < 128) ? (W1 + (size_t)n1 * NCOLS)
                                 : (W1 + (size_t)(n1 - 128) * NCOLS + 128);

    g_W4[(jp * 8 + kb) * 32 + lane] =
        make_uint4(f2h2(r0[k0], r0[k0 + 1]), f2h2(r0[k0 + 8], r0[k0 + 9]),
                   f2h2(r1[k0], r1[k0 + 1]), f2h2(r1[k0 + 8], r1[k0 + 9]));
}

// ============================================================================
// Kernel 1: P = x @ Bmat^T (fp16 m16n8k16, fp32 accum).
// x converted fp32->fp16 into smem once per CTA; A via ldmatrix, B from g_W4.
// grid = N_CTAS (64 rows each), block = 256 (8 warps: 2 M x 4 N, tile 32x64).
// b1 folded into cols < 128. P stored fp16.
// ============================================================================
__global__ __launch_bounds__(256, 2) void precompute_kernel(
    const float* __restrict__ x,
    const float* __restrict__ b1,
    int nN)
{
    __shared__ __half sA[64][SA];        // 17408 B

    const int tid  = threadIdx.x;
    const int wid  = tid >> 5;
    const int lane = tid & 31;
    const int wmg  = wid & 1;
    const int wng  = wid >> 1;
    const int wm   = wmg * 32;
    const int wjt  = wng * 8;
    const int r    = lane >> 2;
    const int c2   = (lane & 3) * 2;
    const int m0   = blockIdx.x * 64;

    // ---- fill smem A tile: 64 rows x 128 cols fp16 ----
    {
        const int rr = tid >> 2;          // row 0..63
        const int q  = tid & 3;           // 32-col quarter
        const int m  = m0 + rr;
        u32 buf[16];
        if (m < nN) {
            const float4* src =
                reinterpret_cast<const float4*>(x + (size_t)m * D + q * 32);
            #pragma unroll
            for (int i = 0; i < 8; i++) {
                float4 v = src[i];
                buf[2 * i]     = f2h2(v.x, v.y);
                buf[2 * i + 1] = f2h2(v.z, v.w);
            }
        } else {
            #pragma unroll
            for (int i = 0; i < 16; i++) buf[i] = 0u;
        }
        uint4* dst = reinterpret_cast<uint4*>(&sA[rr][q * 32]);
        #pragma unroll
        for (int i = 0; i < 4; i++)
            dst[i] = make_uint4(buf[4 * i], buf[4 * i + 1],
                                buf[4 * i + 2], buf[4 * i + 3]);
    }
    __syncthreads();

    float acc[2][8][4];
    #pragma unroll
    for (int i = 0; i < 2; i++)
        #pragma unroll
        for (int j = 0; j < 8; j++)
            #pragma unroll
            for (int q = 0; q < 4; q++) acc[i][j][q] = 0.f;

    const u32 sAu = smem_u32(&sA[0][0]);

    #pragma unroll
    for (int kb = 0; kb < 8; kb++) {
        u32 a[2][4];
        #pragma unroll
        for (int i = 0; i < 2; i++) {
            u32 addr = sAu + (((wm + i * 16 + (lane & 15)) * SA
                               + kb * 16 + (lane >> 4) * 8) << 1);
            LDMATRIX_X4(a[i][0], a[i][1], a[i][2], a[i][3], addr);
        }
        #pragma unroll
        for (int jp = 0; jp < 4; jp++) {
            uint4 B = g_W4[(((wjt >> 1) + jp) * 8 + kb) * 32 + lane];
            mma_f16(acc[0][2 * jp],     a[0], B.x, B.y);
            mma_f16(acc[1][2 * jp],     a[1], B.x, B.y);
            mma_f16(acc[0][2 * jp + 1], a[0], B.z, B.w);
            mma_f16(acc[1][2 * jp + 1], a[1], B.z, B.w);
        }
    }

    // ---- epilogue: + b1 (cols<128 only), fp16 store ----
    #pragma unroll
    for (int j = 0; j < 8; j++) {
        const int col = (wjt + j) * 8 + c2;
        float2 bias = make_float2(0.f, 0.f);
        if (col < 128)
            bias = *reinterpret_cast<const float2*>(b1 + col);
        #pragma unroll
        for (int i = 0; i < 2; i++) {
            const int mA = m0 + wm + i * 16 + r;
            if (mA < nN) {
                *reinterpret_cast<u32*>(&g_Ph[(size_t)mA * NCOLS + col]) =
                    f2h2(acc[i][j][0] + bias.x, acc[i][j][1] + bias.y);
            }
            const int mB = mA + 8;
            if (mB < nN) {
                *reinterpret_cast<u32*>(&g_Ph[(size_t)mB * NCOLS + col]) =
                    f2h2(acc[i][j][2] + bias.x, acc[i][j][3] + bias.y);
            }
        }
    }
}

// ============================================================================
// Kernel 2: per-edge MLP tail (R10 config: 8 lanes/edge, 4 slots, ILP=2 ->
// 8 edges per warp iteration).
//   v = sum_j max(PA[src][j] + PB[dst][j], 0) * w2[j]    (b1 already in PA)
//   out[e] = sigmoid(relu(v + b2))
// ============================================================================
__device__ __forceinline__ float dot16(uint4 ua, uint4 uc, const float* w) {
    const __half2 z2 = __float2half2_rn(0.f);
    const __half2* a2 = reinterpret_cast<const __half2*>(&ua);
    const __half2* c2 = reinterpret_cast<const __half2*>(&uc);
    float v = 0.f;
    #pragma unroll
    for (int i = 0; i < 4; i++) {
        __half2 h = __hmax2(__hadd2(a2[i], c2[i]), z2);
        float2 f = __half22float2(h);
        v = fmaf(f.x, w[2 * i], v);
        v = fmaf(f.y, w[2 * i + 1], v);
    }
    return v;
}

__global__ __launch_bounds__(256) void edge_kernel(
    const void* __restrict__ edge_index,
    const float* __restrict__ W2,
    const float* __restrict__ b2,
    float* __restrict__ out,
    int E)
{
    const int lane   = threadIdx.x & 31;
    const int slot   = lane >> 3;
    const int sub    = lane & 7;
    const int warp   = (blockIdx.x * blockDim.x + threadIdx.x) >> 5;
    const int nwarps = (gridDim.x * blockDim.x) >> 5;

    // dtype sniff: LE int64 (<2^31) => all odd 32-bit words zero
    const int* ei32 = (const int*)edge_index;
    int det = 0;
    #pragma unroll
    for (int i = 1; i < 16; i += 2) det |= __ldg(&ei32[i]);
    const bool is64 = (det == 0);
    const long long* ei64 = (const long long*)edge_index;

    float w0[8], w1[8];
    {
        const float4* w4 = reinterpret_cast<const float4*>(W2);
        float4 p0 = w4[sub * 2], p1 = w4[sub * 2 + 1];
        float4 p2 = w4[16 + sub * 2], p3 = w4[16 + sub * 2 + 1];
        w0[0]=p0.x; w0[1]=p0.y; w0[2]=p0.z; w0[3]=p0.w;
        w0[4]=p1.x; w0[5]=p1.y; w0[6]=p1.z; w0[7]=p1.w;
        w1[0]=p2.x; w1[1]=p2.y; w1[2]=p2.z; w1[3]=p2.w;
        w1[4]=p3.x; w1[5]=p3.y; w1[6]=p3.z; w1[7]=p3.w;
    }
    const float b2v = *b2;
    const __half* Ph = g_Ph;

    for (int eb = warp * 8; eb < E; eb += nwarps * 8) {
        const int e0r = eb + slot;
        const int e1r = eb + 4 + slot;
        const int e0 = (e0r < E) ? e0r : (E - 1);
        const int e1 = (e1r < E) ? e1r : (E - 1);

        int s0, t0, s1, t1;
        if (is64) {
            s0 = (int)ei64[e0]; t0 = (int)ei64[E + e0];
            s1 = (int)ei64[e1]; t1 = (int)ei64[E + e1];
        } else {
            s0 = ei32[e0]; t0 = ei32[E + e0];
            s1 = ei32[e1]; t1 = ei32[E + e1];
        }

        const __half* rA0 = Ph + (size_t)s0 * NCOLS;
        const __half* rC0 = Ph + (size_t)t0 * NCOLS + 128;
        const __half* rA1 = Ph + (size_t)s1 * NCOLS;
        const __half* rC1 = Ph + (size_t)t1 * NCOLS + 128;

        uint4 a00 = *reinterpret_cast<const uint4*>(rA0 + sub * 8);
        uint4 a01 = *reinterpret_cast<const uint4*>(rA0 + 64 + sub * 8);
        uint4 c00 = *reinterpret_cast<const uint4*>(rC0 + sub * 8);
        uint4 c01 = *reinterpret_cast<const uint4*>(rC0 + 64 + sub * 8);
        uint4 a10 = *reinterpret_cast<const uint4*>(rA1 + sub * 8);
        uint4 a11 = *reinterpret_cast<const uint4*>(rA1 + 64 + sub * 8);
        uint4 c10 = *reinterpret_cast<const uint4*>(rC1 + sub * 8);
        uint4 c11 = *reinterpret_cast<const uint4*>(rC1 + 64 + sub * 8);

        float v0 = dot16(a00, c00, w0) + dot16(a01, c01, w1);
        float v1 = dot16(a10, c10, w0) + dot16(a11, c11, w1);

        #pragma unroll
        for (int o = 4; o > 0; o >>= 1) {
            v0 += __shfl_xor_sync(0xFFFFFFFFu, v0, o);
            v1 += __shfl_xor_sync(0xFFFFFFFFu, v1, o);
        }

        if (sub == 0) {
            if (e0r < E) {
                float h = fmaxf(v0 + b2v, 0.f);
                out[e0r] = 1.0f / (1.0f + __expf(-h));
            }
            if (e1r < E) {
                float h = fmaxf(v1 + b2v, 0.f);
                out[e1r] = 1.0f / (1.0f + __expf(-h));
            }
        }
    }
}

// ============================================================================
// Launch
// Inputs: x[f32 N*128], edge_index[2*E i32/i64], W1[f32 128*256], b1[f32 128],
//         W2[f32 128], b2[f32 1]. Output: f32 E.
// ============================================================================
extern "C" void kernel_launch(void* const* d_in, const int* in_sizes, int n_in,
                              void* d_out, int out_size)
{
    const float* x  = (const float*)d_in[0];
    const void*  ei = d_in[1];
    const float* W1 = (const float*)d_in[2];
    const float* b1 = (const float*)d_in[3];
    const float* W2 = (const float*)d_in[4];
    const float* b2 = (const float*)d_in[5];
    float*       out = (float*)d_out;

    const int N = in_sizes[0] / D;   // 100000
    const int E = in_sizes[1] / 2;   // 625000

    prep_w_kernel<<<16, 256>>>(W1);
    precompute_kernel<<<N_CTAS, 256>>>(x, b1, N);
    edge_kernel<<<1184, 256>>>(ei, W2, b2, out, E);
}

// round 13
// speedup vs baseline: 1.0747x; 1.0747x over previous
#include <cuda_runtime.h>
#include <cuda_fp16.h>
#include <math.h>

#define D         128
#define NCOLS     256
#define MAX_NODES 100000
#define N_CTAS    1563                   // ceil(100000 / 64)
#define MAX_MT    (N_CTAS * 4)           // 6252 m-tiles of 16 rows (padded)

typedef unsigned int u32;

// P (layer-1 pre-bias activations, A|B halves; b1 folded into A half), fp16
__device__ __half g_Ph[(size_t)MAX_NODES * NCOLS];
// W1 as paired fp16 B-fragments: ((jp*8 + kb)*32 + lane) -> uint4
__device__ uint4 g_W4[16 * 8 * 32];
// x as fp16 A-fragments: ((mt*8 + kb)*32 + lane) -> uint4 {a0,a1,a2,a3}
__device__ uint4 g_X4[(size_t)MAX_MT * 8 * 32];

// ============================================================================
// helpers
// ============================================================================
__device__ __forceinline__ u32 f2h2(float lo, float hi) {
    u32 r;
    asm("cvt.rn.f16x2.f32 %0, %1, %2;" : "=r"(r) : "f"(hi), "f"(lo));
    return r;
}

__device__ __forceinline__ void mma_f16(float* d, const u32* a, u32 b0, u32 b1) {
    asm volatile(
        "mma.sync.aligned.m16n8k16.row.col.f32.f16.f16.f32 "
        "{%0, %1, %2, %3}, {%4, %5, %6, %7}, {%8, %9}, {%0, %1, %2, %3};"
        : "+f"(d[0]), "+f"(d[1]), "+f"(d[2]), "+f"(d[3])
        : "r"(a[0]), "r"(a[1]), "r"(a[2]), "r"(a[3]), "r"(b0), "r"(b1));
}

// ============================================================================
// Kernel 0 (merged): x -> fp16 A-fragments; blocks 0..15 also convert W1 ->
// paired fp16 B-fragments. grid = MAX_MT, block = 256 (kb x lane).
// ============================================================================
__global__ void prep_kernel(const float* __restrict__ x,
                            const float* __restrict__ W1,
                            int nN)
{
    const int mt   = blockIdx.x;
    const int kb   = threadIdx.x >> 5;
    const int lane = threadIdx.x & 31;
    const int r    = lane >> 2;
    const int k    = kb * 16 + (lane & 3) * 2;

    // ---- W part (first 16 blocks only) ----
    if (mt < 16) {
        const int n0 = mt * 16 + (lane >> 2);
        const int n1 = n0 + 8;
        const int k0 = kb * 16 + (lane & 3) * 2;
        const float* r0 = (n0 < 128) ? (W1 + (size_t)n0 * NCOLS)
                                     : (W1 + (size_t)(n0 - 128) * NCOLS + 128);
        const float* r1 = (n1 < 128) ? (W1 + (size_t)n1 * NCOLS)
                                     : (W1 + (size_t)(n1 - 128) * NCOLS + 128);
        g_W4[(mt * 8 + kb) * 32 + lane] =
            make_uint4(f2h2(r0[k0], r0[k0 + 1]), f2h2(r0[k0 + 8], r0[k0 + 9]),
                       f2h2(r1[k0], r1[k0 + 1]), f2h2(r1[k0 + 8], r1[k0 + 9]));
    }

    // ---- X part (all blocks) ----
    const int m = mt * 16 + r;
    const float2 z = make_float2(0.f, 0.f);
    const float* p0 = x + (size_t)m * D + k;
    const float* p1 = x + (size_t)(m + 8) * D + k;
    float2 v0 = (m < nN)     ? *reinterpret_cast<const float2*>(p0)     : z;
    float2 v2 = (m < nN)     ? *reinterpret_cast<const float2*>(p0 + 8) : z;
    float2 v1 = (m + 8 < nN) ? *reinterpret_cast<const float2*>(p1)     : z;
    float2 v3 = (m + 8 < nN) ? *reinterpret_cast<const float2*>(p1 + 8) : z;

    g_X4[((size_t)mt * 8 + kb) * 32 + lane] =
        make_uint4(f2h2(v0.x, v0.y), f2h2(v1.x, v1.y),
                   f2h2(v2.x, v2.y), f2h2(v3.x, v3.y));
}

// ============================================================================
// Kernel 1: P = x @ Bmat^T (fp16 m16n8k16, fp32 accum), pure fragment loads.
// grid = N_CTAS (64 rows each), block = 256 (8 warps: 2 M x 4 N, tile 32x64).
// b1 folded into cols < 128. P stored fp16.  (R10 verbatim)
// ============================================================================
__global__ __launch_bounds__(256, 2) void precompute_kernel(
    const float* __restrict__ b1, int nN)
{
    const int tid  = threadIdx.x;
    const int wid  = tid >> 5;
    const int lane = tid & 31;
    const int wmg  = wid & 1;
    const int wng  = wid >> 1;
    const int wm   = wmg * 32;
    const int wjt  = wng * 8;
    const int r    = lane >> 2;
    const int c2   = (lane & 3) * 2;
    const int m0   = blockIdx.x * 64;
    const int mtb  = blockIdx.x * 4 + wmg * 2;

    float acc[2][8][4];
    #pragma unroll
    for (int i = 0; i < 2; i++)
        #pragma unroll
        for (int j = 0; j < 8; j++)
            #pragma unroll
            for (int q = 0; q < 4; q++) acc[i][j][q] = 0.f;

    #pragma unroll
    for (int kb = 0; kb < 8; kb++) {
        u32 a[2][4];
        #pragma unroll
        for (int i = 0; i < 2; i++) {
            uint4 A = g_X4[((size_t)(mtb + i) * 8 + kb) * 32 + lane];
            a[i][0] = A.x; a[i][1] = A.y; a[i][2] = A.z; a[i][3] = A.w;
        }
        #pragma unroll
        for (int jp = 0; jp < 4; jp++) {
            uint4 B = g_W4[(((wjt >> 1) + jp) * 8 + kb) * 32 + lane];
            mma_f16(acc[0][2 * jp],     a[0], B.x, B.y);
            mma_f16(acc[1][2 * jp],     a[1], B.x, B.y);
            mma_f16(acc[0][2 * jp + 1], a[0], B.z, B.w);
            mma_f16(acc[1][2 * jp + 1], a[1], B.z, B.w);
        }
    }

    #pragma unroll
    for (int j = 0; j < 8; j++) {
        const int col = (wjt + j) * 8 + c2;
        float2 bias = make_float2(0.f, 0.f);
        if (col < 128)
            bias = *reinterpret_cast<const float2*>(b1 + col);
        #pragma unroll
        for (int i = 0; i < 2; i++) {
            const int mA = m0 + wm + i * 16 + r;
            if (mA < nN) {
                *reinterpret_cast<u32*>(&g_Ph[(size_t)mA * NCOLS + col]) =
                    f2h2(acc[i][j][0] + bias.x, acc[i][j][1] + bias.y);
            }
            const int mB = mA + 8;
            if (mB < nN) {
                *reinterpret_cast<u32*>(&g_Ph[(size_t)mB * NCOLS + col]) =
                    f2h2(acc[i][j][2] + bias.x, acc[i][j][3] + bias.y);
            }
        }
    }
}

// ============================================================================
// Kernel 2: per-edge MLP tail. 8 lanes per edge, 4 edge-slots per warp,
// ILP=3 (12 edges per warp iteration).
//   v = sum_j max(PA[src][j] + PB[dst][j], 0) * w2[j]    (b1 already in PA)
//   out[e] = sigmoid(relu(v + b2))
// ============================================================================
__device__ __forceinline__ float dot16(uint4 ua, uint4 uc, const float* w) {
    const __half2 z2 = __float2half2_rn(0.f);
    const __half2* a2 = reinterpret_cast<const __half2*>(&ua);
    const __half2* c2 = reinterpret_cast<const __half2*>(&uc);
    float v = 0.f;
    #pragma unroll
    for (int i = 0; i < 4; i++) {
        __half2 h = __hmax2(__hadd2(a2[i], c2[i]), z2);
        float2 f = __half22float2(h);
        v = fmaf(f.x, w[2 * i], v);
        v = fmaf(f.y, w[2 * i + 1], v);
    }
    return v;
}

__global__ __launch_bounds__(256) void edge_kernel(
    const void* __restrict__ edge_index,
    const float* __restrict__ W2,
    const float* __restrict__ b2,
    float* __restrict__ out,
    int E)
{
    const int lane   = threadIdx.x & 31;
    const int slot   = lane >> 3;
    const int sub    = lane & 7;
    const int warp   = (blockIdx.x * blockDim.x + threadIdx.x) >> 5;
    const int nwarps = (gridDim.x * blockDim.x) >> 5;

    // dtype sniff: LE int64 (<2^31) => all odd 32-bit words zero
    const int* ei32 = (const int*)edge_index;
    int det = 0;
    #pragma unroll
    for (int i = 1; i < 16; i += 2) det |= __ldg(&ei32[i]);
    const bool is64 = (det == 0);
    const long long* ei64 = (const long long*)edge_index;

    float w0[8], w1[8];
    {
        const float4* w4 = reinterpret_cast<const float4*>(W2);
        float4 p0 = w4[sub * 2], p1 = w4[sub * 2 + 1];
        float4 p2 = w4[16 + sub * 2], p3 = w4[16 + sub * 2 + 1];
        w0[0]=p0.x; w0[1]=p0.y; w0[2]=p0.z; w0[3]=p0.w;
        w0[4]=p1.x; w0[5]=p1.y; w0[6]=p1.z; w0[7]=p1.w;
        w1[0]=p2.x; w1[1]=p2.y; w1[2]=p2.z; w1[3]=p2.w;
        w1[4]=p3.x; w1[5]=p3.y; w1[6]=p3.z; w1[7]=p3.w;
    }
    const float b2v = *b2;
    const __half* Ph = g_Ph;

    for (int eb = warp * 12; eb < E; eb += nwarps * 12) {
        int er[3], s[3], t[3];
        #pragma unroll
        for (int q = 0; q < 3; q++) {
            er[q] = eb + q * 4 + slot;
            int e = (er[q] < E) ? er[q] : (E - 1);
            if (is64) { s[q] = (int)ei64[e]; t[q] = (int)ei64[E + e]; }
            else      { s[q] = ei32[e];      t[q] = ei32[E + e]; }
        }

        uint4 a0[3], a1[3], c0[3], c1[3];
        #pragma unroll
        for (int q = 0; q < 3; q++) {
            const __half* rA = Ph + (size_t)s[q] * NCOLS;
            const __half* rC = Ph + (size_t)t[q] * NCOLS + 128;
            a0[q] = *reinterpret_cast<const uint4*>(rA + sub * 8);
            a1[q] = *reinterpret_cast<const uint4*>(rA + 64 + sub * 8);
            c0[q] = *reinterpret_cast<const uint4*>(rC + sub * 8);
            c1[q] = *reinterpret_cast<const uint4*>(rC + 64 + sub * 8);
        }

        float v[3];
        #pragma unroll
        for (int q = 0; q < 3; q++)
            v[q] = dot16(a0[q], c0[q], w0) + dot16(a1[q], c1[q], w1);

        #pragma unroll
        for (int o = 4; o > 0; o >>= 1) {
            #pragma unroll
            for (int q = 0; q < 3; q++)
                v[q] += __shfl_xor_sync(0xFFFFFFFFu, v[q], o);
        }

        if (sub == 0) {
            #pragma unroll
            for (int q = 0; q < 3; q++) {
                if (er[q] < E) {
                    float h = fmaxf(v[q] + b2v, 0.f);
                    out[er[q]] = 1.0f / (1.0f + __expf(-h));
                }
            }
        }
    }
}

// ============================================================================
// Launch
// Inputs: x[f32 N*128], edge_index[2*E i32/i64], W1[f32 128*256], b1[f32 128],
//         W2[f32 128], b2[f32 1]. Output: f32 E.
// ============================================================================
extern "C" void kernel_launch(void* const* d_in, const int* in_sizes, int n_in,
                              void* d_out, int out_size)
{
    const float* x  = (const float*)d_in[0];
    const void*  ei = d_in[1];
    const float* W1 = (const float*)d_in[2];
    const float* b1 = (const float*)d_in[3];
    const float* W2 = (const float*)d_in[4];
    const float* b2 = (const float*)d_in[5];
    float*       out = (float*)d_out;

    const int N = in_sizes[0] / D;   // 100000
    const int E = in_sizes[1] / 2;   // 625000

    prep_kernel<<<MAX_MT, 256>>>(x, W1, N);
    precompute_kernel<<<N_CTAS, 256>>>(b1, N);
    edge_kernel<<<1184, 256>>>(ei, W2, b2, out, E);
}